// round 1
// baseline (speedup 1.0000x reference)
#include <cuda_runtime.h>
#include <math_constants.h>

#define BM 64
#define BN 64
#define DHEAD 128
#define NTHREADS 256
#define SSEQ 4096

// smem layout (floats):
//  Qt  [128][64]  transposed, XOR-swizzled chunks   8192
//  Kt  [128][64]  transposed, XOR-swizzled chunks   8192
//  Vs  [64][128]  row-major                         8192
//  Pt  [64][64]   P transposed, XOR-swizzled        4096
//  mS/lS/aS [64] each                                192
// total 28864 floats = 115456 bytes
#define SMEM_FLOATS 28864

__global__ __launch_bounds__(NTHREADS, 2)
void flash_fwd_kernel(const float* __restrict__ Q,
                      const float* __restrict__ K,
                      const float* __restrict__ V,
                      float* __restrict__ O)
{
    extern __shared__ float smem[];
    float* Qt = smem;
    float* Kt = Qt + 8192;
    float* Vs = Kt + 8192;
    float* Pt = Vs + 8192;
    float* mS = Pt + 4096;
    float* lS = mS + 64;
    float* aS = lS + 64;

    const int tid = threadIdx.x;
    const int b   = blockIdx.y;
    const int m0  = blockIdx.x * BM;

    // scale * log2(e): softmax carried in log2 domain, exp2f -> MUFU.EX2
    const float SL2 = 0.08838834764831845f * 1.4426950408889634f;

    // ---- load Q tile -> Qt (transposed, swizzled) ----
    {
        const float* qb = Q + ((size_t)b * SSEQ + m0) * DHEAD;
        #pragma unroll
        for (int it = 0; it < 8; ++it) {
            int idx = it * NTHREADS + tid;
            int j  = idx >> 5;   // row in tile (0..63)
            int dg = idx & 31;   // d-group (0..31), 4 floats each
            float4 v = *reinterpret_cast<const float4*>(qb + j * DHEAD + dg * 4);
            int jc = j >> 2, jr = j & 3;
            int pc = jc ^ (dg & 15);          // chunk swizzle
            float vv[4] = {v.x, v.y, v.z, v.w};
            #pragma unroll
            for (int c = 0; c < 4; ++c) {
                int d = 4 * dg + c;
                Qt[d * 64 + pc * 4 + jr] = vv[c];
            }
        }
    }
    if (tid < BM) { mS[tid] = -CUDART_INF_F; lS[tid] = 0.0f; }

    float o[8][4];
    #pragma unroll
    for (int r = 0; r < 8; ++r)
        #pragma unroll
        for (int c = 0; c < 4; ++c) o[r][c] = 0.0f;

    const int ty  = tid >> 4,  tx  = tid & 15;   // QK phase: 4x4 tile
    const int ty2 = tid >> 5,  tx2 = tid & 31;   // PV phase: 8 rows x 4 cols

    const float* kb0 = K + (size_t)b * SSEQ * DHEAD;
    const float* vb0 = V + (size_t)b * SSEQ * DHEAD;

    for (int n0 = 0; n0 < SSEQ; n0 += BN) {
        __syncthreads();   // previous PV finished reading Vs/Pt

        // ---- load K tile -> Kt (transposed, swizzled), V tile -> Vs ----
        {
            const float* kb = kb0 + (size_t)n0 * DHEAD;
            const float* vb = vb0 + (size_t)n0 * DHEAD;
            #pragma unroll
            for (int it = 0; it < 8; ++it) {
                int idx = it * NTHREADS + tid;
                int j  = idx >> 5;
                int dg = idx & 31;
                float4 kv = *reinterpret_cast<const float4*>(kb + j * DHEAD + dg * 4);
                int jc = j >> 2, jr = j & 3;
                int pc = jc ^ (dg & 15);
                float kk[4] = {kv.x, kv.y, kv.z, kv.w};
                #pragma unroll
                for (int c = 0; c < 4; ++c) {
                    int d = 4 * dg + c;
                    Kt[d * 64 + pc * 4 + jr] = kk[c];
                }
                float4 vv = *reinterpret_cast<const float4*>(vb + j * DHEAD + dg * 4);
                *reinterpret_cast<float4*>(Vs + j * DHEAD + dg * 4) = vv;
            }
        }
        __syncthreads();

        // ---- S = Q K^T : 4x4 per thread, rank-1 updates over d ----
        float s[4][4];
        #pragma unroll
        for (int i = 0; i < 4; ++i)
            #pragma unroll
            for (int jj = 0; jj < 4; ++jj) s[i][jj] = 0.0f;

        #pragma unroll 4
        for (int d = 0; d < DHEAD; ++d) {
            int sw = (d >> 2) & 15;
            float4 qv = *reinterpret_cast<const float4*>(Qt + d * 64 + ((ty ^ sw) << 2));
            float4 kv = *reinterpret_cast<const float4*>(Kt + d * 64 + ((tx ^ sw) << 2));
            float qa[4] = {qv.x, qv.y, qv.z, qv.w};
            float ka[4] = {kv.x, kv.y, kv.z, kv.w};
            #pragma unroll
            for (int i = 0; i < 4; ++i)
                #pragma unroll
                for (int jj = 0; jj < 4; ++jj)
                    s[i][jj] = fmaf(qa[i], ka[jj], s[i][jj]);
        }

        // ---- online softmax (log2 domain), row stats via 16-lane shfl ----
        #pragma unroll
        for (int i = 0; i < 4; ++i) {
            int r = 4 * ty + i;
            float t0 = s[i][0] * SL2;
            float t1 = s[i][1] * SL2;
            float t2 = s[i][2] * SL2;
            float t3 = s[i][3] * SL2;
            float mx = fmaxf(fmaxf(t0, t1), fmaxf(t2, t3));
            #pragma unroll
            for (int off = 1; off < 16; off <<= 1)
                mx = fmaxf(mx, __shfl_xor_sync(0xffffffffu, mx, off));
            float mold = mS[r];
            float mnew = fmaxf(mold, mx);
            float p0 = exp2f(t0 - mnew);
            float p1 = exp2f(t1 - mnew);
            float p2 = exp2f(t2 - mnew);
            float p3 = exp2f(t3 - mnew);
            s[i][0] = p0; s[i][1] = p1; s[i][2] = p2; s[i][3] = p3;
            float rs = (p0 + p1) + (p2 + p3);
            #pragma unroll
            for (int off = 1; off < 16; off <<= 1)
                rs += __shfl_xor_sync(0xffffffffu, rs, off);
            if (tx == 0) {
                float alpha = exp2f(mold - mnew);   // 0 on first tile (mold=-inf)
                mS[r] = mnew;
                lS[r] = lS[r] * alpha + rs;
                aS[r] = alpha;
            }
        }

        // ---- store P -> Pt (transposed, swizzled) ----
        #pragma unroll
        for (int jj = 0; jj < 4; ++jj) {
            int j  = 4 * tx + jj;
            int pc = ty ^ tx;                  // (j>>2)==tx for jj<4
            float4 pv = make_float4(s[0][jj], s[1][jj], s[2][jj], s[3][jj]);
            *reinterpret_cast<float4*>(Pt + j * 64 + (pc << 2)) = pv;
        }
        __syncthreads();

        // ---- O = alpha*O + P V : 8x4 per thread ----
        float a[8];
        #pragma unroll
        for (int r = 0; r < 8; ++r) a[r] = aS[8 * ty2 + r];
        #pragma unroll
        for (int r = 0; r < 8; ++r)
            #pragma unroll
            for (int c = 0; c < 4; ++c) o[r][c] *= a[r];

        #pragma unroll 4
        for (int j = 0; j < BN; ++j) {
            int sw = (j >> 2) & 15;
            float4 p0 = *reinterpret_cast<const float4*>(Pt + j * 64 + ((( 2 * ty2     ) ^ sw) << 2));
            float4 p1 = *reinterpret_cast<const float4*>(Pt + j * 64 + (((2 * ty2 + 1) ^ sw) << 2));
            float4 vv = *reinterpret_cast<const float4*>(Vs + j * DHEAD + 4 * tx2);
            float pa[8] = {p0.x, p0.y, p0.z, p0.w, p1.x, p1.y, p1.z, p1.w};
            float va[4] = {vv.x, vv.y, vv.z, vv.w};
            #pragma unroll
            for (int r = 0; r < 8; ++r)
                #pragma unroll
                for (int c = 0; c < 4; ++c)
                    o[r][c] = fmaf(pa[r], va[c], o[r][c]);
        }
    }

    __syncthreads();
    // ---- epilogue: normalize by l, coalesced float4 stores ----
    #pragma unroll
    for (int r = 0; r < 8; ++r) {
        int row = 8 * ty2 + r;
        float inv = 1.0f / lS[row];
        float4 ov = make_float4(o[r][0] * inv, o[r][1] * inv, o[r][2] * inv, o[r][3] * inv);
        *reinterpret_cast<float4*>(O + ((size_t)b * SSEQ + m0 + row) * DHEAD + 4 * tx2) = ov;
    }
}

extern "C" void kernel_launch(void* const* d_in, const int* in_sizes, int n_in,
                              void* d_out, int out_size)
{
    const float* q = (const float*)d_in[0];
    const float* k = (const float*)d_in[1];
    const float* v = (const float*)d_in[2];
    float* o = (float*)d_out;

    int B = in_sizes[0] / (SSEQ * DHEAD);   // 4 for this problem
    size_t smem_bytes = SMEM_FLOATS * sizeof(float);
    cudaFuncSetAttribute(flash_fwd_kernel,
                         cudaFuncAttributeMaxDynamicSharedMemorySize,
                         (int)smem_bytes);

    dim3 grid(SSEQ / BM, B);
    flash_fwd_kernel<<<grid, NTHREADS, smem_bytes>>>(q, k, v, o);
}